// round 15
// baseline (speedup 1.0000x reference)
#include <cuda_runtime.h>
#include <cuda_bf16.h>
#include <math.h>
#include <float.h>
#include <stdint.h>

#define NA 12000
#define KNB 32
#define EE (NA*KNB)
#define RR 1500
#define PP 4096
#define MA (2*NA)      /* 24000 atom rows (A then B) */
#define MR (2*RR)      /* 3000 residue rows */
#define LN_EPS 1e-5f
#define NPB 8          /* nodes per edgeconv block */

// ---- scratch (static device globals; no allocation) ----
__device__ __nv_bfloat16 g_Ahi[MA * 384];    // edgeconv out hi [24000,384]
__device__ __nv_bfloat16 g_Alo[MA * 384];
__device__ __nv_bfloat16 g_WThi[512 * 384];  // atom_w^T [512,384]
__device__ __nv_bfloat16 g_WTlo[512 * 384];
__device__ __nv_bfloat16 g_W2hi[512 * 512];  // res_w^T  [512,512]
__device__ __nv_bfloat16 g_W2lo[512 * 512];
__device__ __nv_bfloat16 g_REShi[MR * 512];  // residue max [3000,512]
__device__ __nv_bfloat16 g_RESlo[MR * 512];
__device__ float g_H[MA * 512];       // atom MLP relu output (pre-LN)
__device__ float g_HR[MR * 512];      // res MLP relu output (pre-LN)
__device__ float g_Y[MR];             // per-residue scalar: LN(row) . lin1_w

__device__ __forceinline__ float angle3(float ax, float ay, float az,
                                        float bx, float by, float bz) {
    float cx = ay * bz - az * by;
    float cy = az * bx - ax * bz;
    float cz = ax * by - ay * bx;
    float cn = sqrtf(cx * cx + cy * cy + cz * cz);
    float d  = ax * bx + ay * by + az * bz;
    return atan2f(cn, d);
}

#define MMA16816(c, a, b) \
  asm volatile("mma.sync.aligned.m16n8k16.row.col.f32.bf16.bf16.f32 " \
    "{%0,%1,%2,%3}, {%4,%5,%6,%7}, {%8,%9}, {%0,%1,%2,%3};" \
    : "+f"((c)[0]), "+f"((c)[1]), "+f"((c)[2]), "+f"((c)[3]) \
    : "r"((a)[0]), "r"((a)[1]), "r"((a)[2]), "r"((a)[3]), \
      "r"((b)[0]), "r"((b)[1]))

#define LDMX4(r, addr) \
  asm volatile("ldmatrix.sync.aligned.m8n8.x4.shared.b16 {%0,%1,%2,%3}, [%4];" \
    : "=r"((r)[0]), "=r"((r)[1]), "=r"((r)[2]), "=r"((r)[3]) : "r"(addr))

// packed fp32x2 (Blackwell, sm_100+ plain target)
#define PACKF2(out, lo, hi) \
  asm("mov.b64 %0, {%1, %2};" : "=l"(out) : "f"(lo), "f"(hi))
#define UNPACKF2(lo, hi, in) \
  asm("mov.b64 {%0, %1}, %2;" : "=f"(lo), "=f"(hi) : "l"(in))
#define FFMA2(d, a, b, c) \
  asm("fma.rn.f32x2 %0, %1, %2, %3;" : "=l"(d) : "l"(a), "l"(b), "l"(c))

__device__ __forceinline__ uint32_t smem_u32(const void* p) {
    uint32_t a;
    asm("{ .reg .u64 t; cvta.to.shared.u64 t, %1; cvt.u32.u64 %0, t; }"
        : "=r"(a) : "l"(p));
    return a;
}

// ============================================================================
// Kernel 1: fused PPF + MLP(4->4,LN) + MLP(4->128,LN) + max over 32 edges.
// Layer-2 uses packed f32x2 FMA with float2-pre-packed weights in smem.
// Single zbuf (two syncthreads/node) to keep occupancy high.
// ============================================================================
__global__ __launch_bounds__(128) void edgeconv_kernel(
    const float* __restrict__ posA, const float* __restrict__ nrmA, const int* __restrict__ edgA,
    const float* __restrict__ posB, const float* __restrict__ nrmB, const int* __restrict__ edgB,
    const float* __restrict__ cw1, const float* __restrict__ cb1,
    const float* __restrict__ cg1, const float* __restrict__ cbe1,
    const float* __restrict__ cw2, const float* __restrict__ cb2,
    const float* __restrict__ cg2, const float* __restrict__ cbe2)
{
    const int r    = blockIdx.y;
    const int side = blockIdx.z;
    const float* pos = side ? posB : posA;
    const float* nrm = side ? nrmB : nrmA;
    const int*   edg = side ? edgB : edgA;
    const int tid = threadIdx.x;

    // packed pairs: channel pair (q+8j, q+8j+4) at index p = q*16+j
    __shared__ unsigned long long w2p[256];   // [k][p] : k*64+p
    __shared__ unsigned long long b2p[64];
    __shared__ float g2s[128], be2s[128];
    __shared__ float w1s[16], b1s[4], g1s[4], be1s[4];
    __shared__ float zbuf[32 * 132];
    __shared__ float mus[32], rss[32];

    for (int idx = tid; idx < 256; idx += 128) {
        int k = idx >> 6, p = idx & 63;
        int qq = p >> 4, j = p & 15;
        float a = cw2[r * 512 + k * 128 + qq + 8 * j];
        float b = cw2[r * 512 + k * 128 + qq + 8 * j + 4];
        unsigned long long pk; PACKF2(pk, a, b);
        w2p[idx] = pk;
    }
    if (tid < 64) {
        int qq = tid >> 4, j = tid & 15;
        float a = cb2[r * 128 + qq + 8 * j];
        float b = cb2[r * 128 + qq + 8 * j + 4];
        unsigned long long pk; PACKF2(pk, a, b);
        b2p[tid] = pk;
    }
    g2s[tid]  = cg2[r * 128 + tid];
    be2s[tid] = cbe2[r * 128 + tid];
    if (tid < 16) w1s[tid] = cw1[r * 16 + tid];
    if (tid < 4) {
        b1s[tid]  = cb1[r * 4 + tid];
        g1s[tid]  = cg1[r * 4 + tid];
        be1s[tid] = cbe1[r * 4 + tid];
    }
    __syncthreads();

    const int e = tid >> 2;
    const int q = tid & 3;
    const int lane = tid & 31;
    const int lbase = lane & ~3;
    const float ga = g2s[tid], bb = be2s[tid];

    for (int nn = 0; nn < NPB; nn++) {
        const int node = blockIdx.x * NPB + nn;

        float f0, f1, f2, f3;
        if (q == 0) {
            const int src = __ldg(&edg[r * 2 * EE + node * KNB + e]);
            const float dx = pos[src * 3 + 0] - pos[node * 3 + 0];
            const float dy = pos[src * 3 + 1] - pos[node * 3 + 1];
            const float dz = pos[src * 3 + 2] - pos[node * 3 + 2];
            const float nix = nrm[node * 3 + 0], niy = nrm[node * 3 + 1], niz = nrm[node * 3 + 2];
            const float njx = nrm[src * 3 + 0], njy = nrm[src * 3 + 1], njz = nrm[src * 3 + 2];
            f0 = sqrtf(dx * dx + dy * dy + dz * dz);
            f1 = angle3(nix, niy, niz, dx, dy, dz);
            f2 = angle3(njx, njy, njz, dx, dy, dz);
            f3 = angle3(nix, niy, niz, njx, njy, njz);
        }
        f0 = __shfl_sync(0xffffffffu, f0, lbase);
        f1 = __shfl_sync(0xffffffffu, f1, lbase);
        f2 = __shfl_sync(0xffffffffu, f2, lbase);
        f3 = __shfl_sync(0xffffffffu, f3, lbase);

        float h[4];
#pragma unroll
        for (int k = 0; k < 4; k++) {
            float v = fmaf(f0, w1s[k],
                      fmaf(f1, w1s[4 + k],
                      fmaf(f2, w1s[8 + k],
                      fmaf(f3, w1s[12 + k], b1s[k]))));
            h[k] = fmaxf(v, 0.f);
        }
        float mu1 = 0.25f * (h[0] + h[1] + h[2] + h[3]);
        float var1 = 0.25f * ((h[0]-mu1)*(h[0]-mu1) + (h[1]-mu1)*(h[1]-mu1)
                            + (h[2]-mu1)*(h[2]-mu1) + (h[3]-mu1)*(h[3]-mu1));
        float rs1 = rsqrtf(var1 + LN_EPS);
        float hn[4];
#pragma unroll
        for (int k = 0; k < 4; k++)
            hn[k] = fmaf(g1s[k] * (h[k] - mu1), rs1, be1s[k]);

        // layer 2: packed f32x2, 2 channels (c, c+4) per iteration
        unsigned long long h0p, h1p, h2p, h3p;
        PACKF2(h0p, hn[0], hn[0]);
        PACKF2(h1p, hn[1], hn[1]);
        PACKF2(h2p, hn[2], hn[2]);
        PACKF2(h3p, hn[3], hn[3]);

        float s = 0.f, s2 = 0.f;
#pragma unroll
        for (int j = 0; j < 16; j++) {
            const int p = (q << 4) + j;
            unsigned long long acc = b2p[p];
            FFMA2(acc, h3p, w2p[192 + p], acc);
            FFMA2(acc, h2p, w2p[128 + p], acc);
            FFMA2(acc, h1p, w2p[64 + p], acc);
            FFMA2(acc, h0p, w2p[p], acc);
            float z0, z1; UNPACKF2(z0, z1, acc);
            z0 = fmaxf(z0, 0.f);
            z1 = fmaxf(z1, 0.f);
            const int c0 = q + 8 * j;
            zbuf[e * 132 + c0] = z0;
            zbuf[e * 132 + c0 + 4] = z1;
            s += z0 + z1;
            s2 = fmaf(z0, z0, fmaf(z1, z1, s2));
        }
        s  += __shfl_xor_sync(0xffffffffu, s, 1);
        s  += __shfl_xor_sync(0xffffffffu, s, 2);
        s2 += __shfl_xor_sync(0xffffffffu, s2, 1);
        s2 += __shfl_xor_sync(0xffffffffu, s2, 2);
        if (q == 0) {
            float mu  = s * (1.f / 128.f);
            float var = fmaxf(s2 * (1.f / 128.f) - mu * mu, 0.f);
            mus[e] = mu;
            rss[e] = rsqrtf(var + LN_EPS);
        }
        __syncthreads();

        float m = -FLT_MAX;
#pragma unroll 8
        for (int ee = 0; ee < 32; ee++) {
            float t = (zbuf[ee * 132 + tid] - mus[ee]) * rss[ee];
            m = fmaxf(m, fmaf(ga, t, bb));
        }
        size_t idx = (size_t)(side * NA + node) * 384 + r * 128 + tid;
        __nv_bfloat16 hi = __float2bfloat16(m);
        g_Ahi[idx] = hi;
        g_Alo[idx] = __float2bfloat16(m - __bfloat162float(hi));
        __syncthreads();   // protect zbuf before next node
    }
}

// ============================================================================
// Kernel 1b: transpose + bf16-split  src[K,512] -> dst hi/lo [512,K]
// ============================================================================
__global__ __launch_bounds__(256) void convert_wT_kernel(
    const float* __restrict__ src, __nv_bfloat16* __restrict__ dhi,
    __nv_bfloat16* __restrict__ dlo, int K)
{
    int i = blockIdx.x * 256 + threadIdx.x;
    if (i >= 512 * K) return;
    int n = i / K, k = i % K;
    float v = src[k * 512 + n];
    __nv_bfloat16 hi = __float2bfloat16(v);
    dhi[i] = hi;
    dlo[i] = __float2bfloat16(v - __bfloat162float(hi));
}

// ============================================================================
// Kernel 2: HMMA bf16-split GEMM with ldmatrix fragment loads.
// C[M,512] = relu(A @ BT^T + bias); 3 mma terms -> fp32 accum.
// Block tile 128x64, 8 warps (4m x 2n), warp tile 32x32, BK=32.
// ============================================================================
__global__ __launch_bounds__(256, 2) void gemm_mma_kernel(
    const __nv_bfloat16* __restrict__ Ahi, const __nv_bfloat16* __restrict__ Alo,
    const __nv_bfloat16* __restrict__ BThi, const __nv_bfloat16* __restrict__ BTlo,
    const float* __restrict__ bias, float* __restrict__ C, int M, int K)
{
    __shared__ __align__(16) unsigned char sm[2 * 10240 + 2 * 5120];
    unsigned char* sAhi = sm;
    unsigned char* sAlo = sm + 10240;
    unsigned char* sBhi = sm + 20480;
    unsigned char* sBlo = sm + 25600;

    const int tid = threadIdx.x;
    const int wid = tid >> 5;
    const int lane = tid & 31;
    const int wm = wid & 3;
    const int wn = wid >> 2;
    const int grp = lane >> 2;
    const int tig = lane & 3;
    const int bm = blockIdx.y * 128;
    const int bn = blockIdx.x * 64;

    float acc[2][4][4];
#pragma unroll
    for (int mt = 0; mt < 2; mt++)
#pragma unroll
        for (int nt = 0; nt < 4; nt++)
#pragma unroll
            for (int j = 0; j < 4; j++) acc[mt][nt][j] = 0.f;

    const int lsel = lane >> 3, lrow = lane & 7;
    const uint32_t a_frag_off =
        (uint32_t)((wm * 32 + lrow + (lsel & 1) * 8) * 80 + (lsel >> 1) * 16);
    const uint32_t b_frag_off =
        (uint32_t)((wn * 32 + (lsel >> 1) * 8 + lrow) * 80 + (lsel & 1) * 16);

    const uint32_t sAhi_u = smem_u32(sAhi), sAlo_u = smem_u32(sAlo);
    const uint32_t sBhi_u = smem_u32(sBhi), sBlo_u = smem_u32(sBlo);

    const int nch = K / 32;
    uint4 pah[2], pal[2], pbh, pbl;

    {
#pragma unroll
        for (int it = 0; it < 2; it++) {
            int id = tid + it * 256;
            int row = id >> 2, kq = id & 3;
            int rg = bm + row; if (rg > M - 1) rg = M - 1;
            pah[it] = *(const uint4*)(Ahi + (size_t)rg * K + kq * 8);
            pal[it] = *(const uint4*)(Alo + (size_t)rg * K + kq * 8);
        }
        {
            int row = tid >> 2, kq = tid & 3;
            pbh = *(const uint4*)(BThi + (size_t)(bn + row) * K + kq * 8);
            pbl = *(const uint4*)(BTlo + (size_t)(bn + row) * K + kq * 8);
        }
#pragma unroll
        for (int it = 0; it < 2; it++) {
            int id = tid + it * 256;
            int row = id >> 2, kq = id & 3;
            *(uint4*)(sAhi + row * 80 + kq * 16) = pah[it];
            *(uint4*)(sAlo + row * 80 + kq * 16) = pal[it];
        }
        {
            int row = tid >> 2, kq = tid & 3;
            *(uint4*)(sBhi + row * 80 + kq * 16) = pbh;
            *(uint4*)(sBlo + row * 80 + kq * 16) = pbl;
        }
    }
    __syncthreads();

    for (int ch = 0; ch < nch; ch++) {
        const bool has_next = (ch + 1 < nch);
        if (has_next) {
            const int k0 = (ch + 1) * 32;
#pragma unroll
            for (int it = 0; it < 2; it++) {
                int id = tid + it * 256;
                int row = id >> 2, kq = id & 3;
                int rg = bm + row; if (rg > M - 1) rg = M - 1;
                pah[it] = *(const uint4*)(Ahi + (size_t)rg * K + k0 + kq * 8);
                pal[it] = *(const uint4*)(Alo + (size_t)rg * K + k0 + kq * 8);
            }
            {
                int row = tid >> 2, kq = tid & 3;
                pbh = *(const uint4*)(BThi + (size_t)(bn + row) * K + k0 + kq * 8);
                pbl = *(const uint4*)(BTlo + (size_t)(bn + row) * K + k0 + kq * 8);
            }
        }

#pragma unroll
        for (int kk = 0; kk < 2; kk++) {
            const uint32_t kadd = kk * 32;
            uint32_t ahf[2][4], alf[2][4];
#pragma unroll
            for (int mt = 0; mt < 2; mt++) {
                LDMX4(ahf[mt], sAhi_u + a_frag_off + mt * (16 * 80) + kadd);
                LDMX4(alf[mt], sAlo_u + a_frag_off + mt * (16 * 80) + kadd);
            }
            uint32_t bhf[4][2], blf[4][2];
#pragma unroll
            for (int p = 0; p < 2; p++) {
                uint32_t tmp[4];
                LDMX4(tmp, sBhi_u + b_frag_off + p * (16 * 80) + kadd);
                bhf[2 * p][0] = tmp[0]; bhf[2 * p][1] = tmp[1];
                bhf[2 * p + 1][0] = tmp[2]; bhf[2 * p + 1][1] = tmp[3];
                LDMX4(tmp, sBlo_u + b_frag_off + p * (16 * 80) + kadd);
                blf[2 * p][0] = tmp[0]; blf[2 * p][1] = tmp[1];
                blf[2 * p + 1][0] = tmp[2]; blf[2 * p + 1][1] = tmp[3];
            }
#pragma unroll
            for (int mt = 0; mt < 2; mt++)
#pragma unroll
                for (int nt = 0; nt < 4; nt++) {
                    MMA16816(acc[mt][nt], ahf[mt], bhf[nt]);
                    MMA16816(acc[mt][nt], ahf[mt], blf[nt]);
                    MMA16816(acc[mt][nt], alf[mt], bhf[nt]);
                }
        }

        if (has_next) {
            __syncthreads();
#pragma unroll
            for (int it = 0; it < 2; it++) {
                int id = tid + it * 256;
                int row = id >> 2, kq = id & 3;
                *(uint4*)(sAhi + row * 80 + kq * 16) = pah[it];
                *(uint4*)(sAlo + row * 80 + kq * 16) = pal[it];
            }
            {
                int row = tid >> 2, kq = tid & 3;
                *(uint4*)(sBhi + row * 80 + kq * 16) = pbh;
                *(uint4*)(sBlo + row * 80 + kq * 16) = pbl;
            }
            __syncthreads();
        }
    }

#pragma unroll
    for (int mt = 0; mt < 2; mt++) {
#pragma unroll
        for (int nt = 0; nt < 4; nt++) {
            int row0 = bm + wm * 32 + mt * 16 + grp;
            int col  = bn + wn * 32 + nt * 8 + tig * 2;
            float b0 = bias[col], b1 = bias[col + 1];
            if (row0 < M) {
                float2 o;
                o.x = fmaxf(acc[mt][nt][0] + b0, 0.f);
                o.y = fmaxf(acc[mt][nt][1] + b1, 0.f);
                *(float2*)(C + (size_t)row0 * 512 + col) = o;
            }
            if (row0 + 8 < M) {
                float2 o;
                o.x = fmaxf(acc[mt][nt][2] + b0, 0.f);
                o.y = fmaxf(acc[mt][nt][3] + b1, 0.f);
                *(float2*)(C + (size_t)(row0 + 8) * 512 + col) = o;
            }
        }
    }
}

// ============================================================================
// Kernel 3: fused atom-LN + residue max -> bf16 hi/lo residue features.
// ============================================================================
__global__ __launch_bounds__(256) void ln_resmax_kernel(
    const float* __restrict__ g, const float* __restrict__ be)
{
    const int res = blockIdx.x;
    const int tid = threadIdx.x;
    const int w = tid >> 5, lane = tid & 31;

    __shared__ float buf[8][512];

    const float* hp = g_H + ((size_t)res * 8 + w) * 512;
    float v[16];
    float s = 0.f, s2 = 0.f;
#pragma unroll
    for (int i = 0; i < 16; i++) {
        v[i] = hp[lane + i * 32];
        s += v[i];
        s2 = fmaf(v[i], v[i], s2);
    }
#pragma unroll
    for (int off = 16; off; off >>= 1) {
        s  += __shfl_xor_sync(0xffffffffu, s, off);
        s2 += __shfl_xor_sync(0xffffffffu, s2, off);
    }
    float mu  = s * (1.f / 512.f);
    float var = fmaxf(s2 * (1.f / 512.f) - mu * mu, 0.f);
    float rs  = rsqrtf(var + LN_EPS);
#pragma unroll
    for (int i = 0; i < 16; i++) {
        int c = lane + i * 32;
        buf[w][c] = fmaf(g[c] * (v[i] - mu), rs, be[c]);
    }
    __syncthreads();

#pragma unroll
    for (int rep = 0; rep < 2; rep++) {
        int c = tid + rep * 256;
        float m = buf[0][c];
#pragma unroll
        for (int j = 1; j < 8; j++) m = fmaxf(m, buf[j][c]);
        size_t idx = (size_t)res * 512 + c;
        __nv_bfloat16 hi = __float2bfloat16(m);
        g_REShi[idx] = hi;
        g_RESlo[idx] = __float2bfloat16(m - __bfloat162float(hi));
    }
}

// ============================================================================
// Kernel 4: fused res-LN + lin1 dot
// ============================================================================
__global__ __launch_bounds__(256) void ln_dot_kernel(
    const float* __restrict__ g, const float* __restrict__ be,
    const float* __restrict__ w1)
{
    const int row = blockIdx.x * 8 + (threadIdx.x >> 5);
    const int lane = threadIdx.x & 31;
    if (row >= MR) return;
    const float* hp = g_HR + (size_t)row * 512;

    float v[16];
    float s = 0.f, s2 = 0.f;
#pragma unroll
    for (int i = 0; i < 16; i++) {
        v[i] = hp[lane + i * 32];
        s += v[i];
        s2 = fmaf(v[i], v[i], s2);
    }
#pragma unroll
    for (int off = 16; off; off >>= 1) {
        s  += __shfl_xor_sync(0xffffffffu, s, off);
        s2 += __shfl_xor_sync(0xffffffffu, s2, off);
    }
    float mu  = s * (1.f / 512.f);
    float var = fmaxf(s2 * (1.f / 512.f) - mu * mu, 0.f);
    float rs  = rsqrtf(var + LN_EPS);

    float acc = 0.f;
#pragma unroll
    for (int i = 0; i < 16; i++) {
        int c = lane + i * 32;
        float x = fmaf(g[c] * (v[i] - mu), rs, be[c]);
        acc = fmaf(x, w1[c], acc);
    }
#pragma unroll
    for (int off = 16; off; off >>= 1)
        acc += __shfl_xor_sync(0xffffffffu, acc, off);
    if (lane == 0) g_Y[row] = acc;
}

// ============================================================================
// Kernel 5: pair head
// ============================================================================
__global__ __launch_bounds__(256) void pair_kernel(
    const int* __restrict__ srcI, const int* __restrict__ tgtI,
    const float* __restrict__ b1, float* __restrict__ out)
{
    const int p = blockIdx.x * 256 + threadIdx.x;
    if (p >= PP) return;
    float x = g_Y[srcI[p]] - g_Y[RR + tgtI[p]] + b1[0];
    out[p] = 1.f / (1.f + expf(-x));
}

// ============================================================================
extern "C" void kernel_launch(void* const* d_in, const int* in_sizes, int n_in,
                              void* d_out, int out_size)
{
    const float* posA = (const float*)d_in[0];
    const float* nrmA = (const float*)d_in[1];
    const float* posB = (const float*)d_in[2];
    const float* nrmB = (const float*)d_in[3];
    const int*   edgA = (const int*)d_in[4];
    const int*   edgB = (const int*)d_in[5];
    const int*   srcI = (const int*)d_in[8];
    const int*   tgtI = (const int*)d_in[9];

    int w = (in_sizes[10] == 48) ? 10 : 11;
    const float* cw1   = (const float*)d_in[w++];
    const float* cb1   = (const float*)d_in[w++];
    const float* cg1   = (const float*)d_in[w++];
    const float* cbe1  = (const float*)d_in[w++];
    const float* cw2   = (const float*)d_in[w++];
    const float* cb2   = (const float*)d_in[w++];
    const float* cg2   = (const float*)d_in[w++];
    const float* cbe2  = (const float*)d_in[w++];
    const float* atomW = (const float*)d_in[w++];
    const float* atomB = (const float*)d_in[w++];
    const float* atomG = (const float*)d_in[w++];
    const float* atomBe= (const float*)d_in[w++];
    const float* resW  = (const float*)d_in[w++];
    const float* resB  = (const float*)d_in[w++];
    const float* resG  = (const float*)d_in[w++];
    const float* resBe = (const float*)d_in[w++];
    const float* lin1W = (const float*)d_in[w++];
    const float* lin1B = (const float*)d_in[w++];

    float* out = (float*)d_out;

    __nv_bfloat16 *wthi, *wtlo, *w2hi, *w2lo, *ahi, *alo, *rhi, *rlo;
    cudaGetSymbolAddress((void**)&wthi, g_WThi);
    cudaGetSymbolAddress((void**)&wtlo, g_WTlo);
    cudaGetSymbolAddress((void**)&w2hi, g_W2hi);
    cudaGetSymbolAddress((void**)&w2lo, g_W2lo);
    cudaGetSymbolAddress((void**)&ahi,  g_Ahi);
    cudaGetSymbolAddress((void**)&alo,  g_Alo);
    cudaGetSymbolAddress((void**)&rhi,  g_REShi);
    cudaGetSymbolAddress((void**)&rlo,  g_RESlo);
    float *gH, *gHR;
    cudaGetSymbolAddress((void**)&gH,  g_H);
    cudaGetSymbolAddress((void**)&gHR, g_HR);

    // 1. edge convs -> g_Ahi/g_Alo [24000,384] bf16 split
    edgeconv_kernel<<<dim3(NA / NPB, 3, 2), 128>>>(
        posA, nrmA, edgA, posB, nrmB, edgB,
        cw1, cb1, cg1, cbe1, cw2, cb2, cg2, cbe2);
    // 1b. weight transposes + splits
    convert_wT_kernel<<<(512 * 384 + 255) / 256, 256>>>(atomW, wthi, wtlo, 384);
    convert_wT_kernel<<<(512 * 512 + 255) / 256, 256>>>(resW,  w2hi, w2lo, 512);
    // 2. atom MLP (HMMA + ldmatrix) -> g_H
    gemm_mma_kernel<<<dim3(8, (MA + 127) / 128), 256>>>(
        ahi, alo, wthi, wtlo, atomB, gH, MA, 384);
    // 3. fused atom-LN + residue max -> g_REShi/lo
    ln_resmax_kernel<<<MR, 256>>>(atomG, atomBe);
    // 4. res MLP (HMMA + ldmatrix) -> g_HR
    gemm_mma_kernel<<<dim3(8, (MR + 127) / 128), 256>>>(
        rhi, rlo, w2hi, w2lo, resB, gHR, MR, 512);
    // 5. fused res-LN + lin1 dot -> g_Y
    ln_dot_kernel<<<(MR + 7) / 8, 256>>>(resG, resBe, lin1W);
    // 6. pair head
    pair_kernel<<<(PP + 255) / 256, 256>>>(srcI, tgtI, lin1B, out);
}

// round 16
// speedup vs baseline: 1.8858x; 1.8858x over previous
#include <cuda_runtime.h>
#include <cuda_bf16.h>
#include <math.h>
#include <float.h>
#include <stdint.h>

#define NA 12000
#define KNB 32
#define EE (NA*KNB)
#define RR 1500
#define PP 4096
#define MA (2*NA)      /* 24000 atom rows (A then B) */
#define MR (2*RR)      /* 3000 residue rows */
#define LN_EPS 1e-5f
#define NPB 8          /* nodes per edgeconv block */

// ---- scratch (static device globals; no allocation) ----
__device__ __nv_bfloat16 g_Ahi[MA * 384];    // edgeconv out hi [24000,384]
__device__ __nv_bfloat16 g_Alo[MA * 384];
__device__ __nv_bfloat16 g_WThi[512 * 384];  // atom_w^T [512,384]
__device__ __nv_bfloat16 g_WTlo[512 * 384];
__device__ __nv_bfloat16 g_W2hi[512 * 512];  // res_w^T  [512,512]
__device__ __nv_bfloat16 g_W2lo[512 * 512];
__device__ __nv_bfloat16 g_REShi[MR * 512];  // residue max [3000,512]
__device__ __nv_bfloat16 g_RESlo[MR * 512];
__device__ float g_H[MA * 512];       // atom MLP relu output (pre-LN)
__device__ float g_HR[MR * 512];      // res MLP relu output (pre-LN)
__device__ float g_Y[MR];             // per-residue scalar: LN(row) . lin1_w

__device__ __forceinline__ float angle3(float ax, float ay, float az,
                                        float bx, float by, float bz) {
    float cx = ay * bz - az * by;
    float cy = az * bx - ax * bz;
    float cz = ax * by - ay * bx;
    float cn = sqrtf(cx * cx + cy * cy + cz * cz);
    float d  = ax * bx + ay * by + az * bz;
    return atan2f(cn, d);
}

#define MMA16816(c, a, b) \
  asm volatile("mma.sync.aligned.m16n8k16.row.col.f32.bf16.bf16.f32 " \
    "{%0,%1,%2,%3}, {%4,%5,%6,%7}, {%8,%9}, {%0,%1,%2,%3};" \
    : "+f"((c)[0]), "+f"((c)[1]), "+f"((c)[2]), "+f"((c)[3]) \
    : "r"((a)[0]), "r"((a)[1]), "r"((a)[2]), "r"((a)[3]), \
      "r"((b)[0]), "r"((b)[1]))

#define LDMX4(r, addr) \
  asm volatile("ldmatrix.sync.aligned.m8n8.x4.shared.b16 {%0,%1,%2,%3}, [%4];" \
    : "=r"((r)[0]), "=r"((r)[1]), "=r"((r)[2]), "=r"((r)[3]) : "r"(addr))

__device__ __forceinline__ uint32_t smem_u32(const void* p) {
    uint32_t a;
    asm("{ .reg .u64 t; cvta.to.shared.u64 t, %1; cvt.u32.u64 %0, t; }"
        : "=r"(a) : "l"(p));
    return a;
}

// ============================================================================
// Kernel 1: fused PPF + MLP(4->4,LN) + MLP(4->128,LN) + max over 32 edges.
// (round-10 form: scalar fp32 layer-2, single zbuf, two syncthreads/node)
// ============================================================================
__global__ __launch_bounds__(128) void edgeconv_kernel(
    const float* __restrict__ posA, const float* __restrict__ nrmA, const int* __restrict__ edgA,
    const float* __restrict__ posB, const float* __restrict__ nrmB, const int* __restrict__ edgB,
    const float* __restrict__ cw1, const float* __restrict__ cb1,
    const float* __restrict__ cg1, const float* __restrict__ cbe1,
    const float* __restrict__ cw2, const float* __restrict__ cb2,
    const float* __restrict__ cg2, const float* __restrict__ cbe2)
{
    const int r    = blockIdx.y;
    const int side = blockIdx.z;
    const float* pos = side ? posB : posA;
    const float* nrm = side ? nrmB : nrmA;
    const int*   edg = side ? edgB : edgA;
    const int tid = threadIdx.x;

    __shared__ float w2s[512], b2s[128], g2s[128], be2s[128];
    __shared__ float w1s[16], b1s[4], g1s[4], be1s[4];
    __shared__ float zbuf[32 * 132];
    __shared__ float mus[32], rss[32];

    for (int i = tid; i < 512; i += 128) w2s[i] = cw2[r * 512 + i];
    b2s[tid]  = cb2[r * 128 + tid];
    g2s[tid]  = cg2[r * 128 + tid];
    be2s[tid] = cbe2[r * 128 + tid];
    if (tid < 16) w1s[tid] = cw1[r * 16 + tid];
    if (tid < 4) {
        b1s[tid]  = cb1[r * 4 + tid];
        g1s[tid]  = cg1[r * 4 + tid];
        be1s[tid] = cbe1[r * 4 + tid];
    }
    __syncthreads();

    const int e = tid >> 2;
    const int q = tid & 3;
    const int lane = tid & 31;
    const int lbase = lane & ~3;
    const float ga = g2s[tid], bb = be2s[tid];

    for (int nn = 0; nn < NPB; nn++) {
        const int node = blockIdx.x * NPB + nn;

        float f0, f1, f2, f3;
        if (q == 0) {
            const int src = __ldg(&edg[r * 2 * EE + node * KNB + e]);
            const float dx = pos[src * 3 + 0] - pos[node * 3 + 0];
            const float dy = pos[src * 3 + 1] - pos[node * 3 + 1];
            const float dz = pos[src * 3 + 2] - pos[node * 3 + 2];
            const float nix = nrm[node * 3 + 0], niy = nrm[node * 3 + 1], niz = nrm[node * 3 + 2];
            const float njx = nrm[src * 3 + 0], njy = nrm[src * 3 + 1], njz = nrm[src * 3 + 2];
            f0 = sqrtf(dx * dx + dy * dy + dz * dz);
            f1 = angle3(nix, niy, niz, dx, dy, dz);
            f2 = angle3(njx, njy, njz, dx, dy, dz);
            f3 = angle3(nix, niy, niz, njx, njy, njz);
        }
        f0 = __shfl_sync(0xffffffffu, f0, lbase);
        f1 = __shfl_sync(0xffffffffu, f1, lbase);
        f2 = __shfl_sync(0xffffffffu, f2, lbase);
        f3 = __shfl_sync(0xffffffffu, f3, lbase);

        float h[4];
#pragma unroll
        for (int k = 0; k < 4; k++) {
            float v = fmaf(f0, w1s[k],
                      fmaf(f1, w1s[4 + k],
                      fmaf(f2, w1s[8 + k],
                      fmaf(f3, w1s[12 + k], b1s[k]))));
            h[k] = fmaxf(v, 0.f);
        }
        float mu1 = 0.25f * (h[0] + h[1] + h[2] + h[3]);
        float var1 = 0.25f * ((h[0]-mu1)*(h[0]-mu1) + (h[1]-mu1)*(h[1]-mu1)
                            + (h[2]-mu1)*(h[2]-mu1) + (h[3]-mu1)*(h[3]-mu1));
        float rs1 = rsqrtf(var1 + LN_EPS);
        float hn[4];
#pragma unroll
        for (int k = 0; k < 4; k++)
            hn[k] = fmaf(g1s[k] * (h[k] - mu1), rs1, be1s[k]);

        float s = 0.f, s2 = 0.f;
#pragma unroll
        for (int c = q; c < 128; c += 4) {
            float z = fmaf(hn[0], w2s[c],
                      fmaf(hn[1], w2s[128 + c],
                      fmaf(hn[2], w2s[256 + c],
                      fmaf(hn[3], w2s[384 + c], b2s[c]))));
            z = fmaxf(z, 0.f);
            zbuf[e * 132 + c] = z;
            s += z;
            s2 = fmaf(z, z, s2);
        }
        s  += __shfl_xor_sync(0xffffffffu, s, 1);
        s  += __shfl_xor_sync(0xffffffffu, s, 2);
        s2 += __shfl_xor_sync(0xffffffffu, s2, 1);
        s2 += __shfl_xor_sync(0xffffffffu, s2, 2);
        if (q == 0) {
            float mu  = s * (1.f / 128.f);
            float var = fmaxf(s2 * (1.f / 128.f) - mu * mu, 0.f);
            mus[e] = mu;
            rss[e] = rsqrtf(var + LN_EPS);
        }
        __syncthreads();

        float m = -FLT_MAX;
#pragma unroll 8
        for (int ee = 0; ee < 32; ee++) {
            float t = (zbuf[ee * 132 + tid] - mus[ee]) * rss[ee];
            m = fmaxf(m, fmaf(ga, t, bb));
        }
        size_t idx = (size_t)(side * NA + node) * 384 + r * 128 + tid;
        __nv_bfloat16 hi = __float2bfloat16(m);
        g_Ahi[idx] = hi;
        g_Alo[idx] = __float2bfloat16(m - __bfloat162float(hi));
        __syncthreads();   // protect zbuf before next node
    }
}

// ============================================================================
// Kernel 1b: transpose + bf16-split  src[K,512] -> dst hi/lo [512,K]
// ============================================================================
__global__ __launch_bounds__(256) void convert_wT_kernel(
    const float* __restrict__ src, __nv_bfloat16* __restrict__ dhi,
    __nv_bfloat16* __restrict__ dlo, int K)
{
    int i = blockIdx.x * 256 + threadIdx.x;
    if (i >= 512 * K) return;
    int n = i / K, k = i % K;
    float v = src[k * 512 + n];
    __nv_bfloat16 hi = __float2bfloat16(v);
    dhi[i] = hi;
    dlo[i] = __float2bfloat16(v - __bfloat162float(hi));
}

// ============================================================================
// Kernel 2: HMMA bf16-split GEMM with ldmatrix fragment loads.
// C[M,512] = relu(A @ BT^T + bias); 3 mma terms -> fp32 accum.
// Block tile 128x64, 8 warps (4m x 2n), warp tile 32x32, BK=32.
// ============================================================================
__global__ __launch_bounds__(256, 2) void gemm_mma_kernel(
    const __nv_bfloat16* __restrict__ Ahi, const __nv_bfloat16* __restrict__ Alo,
    const __nv_bfloat16* __restrict__ BThi, const __nv_bfloat16* __restrict__ BTlo,
    const float* __restrict__ bias, float* __restrict__ C, int M, int K)
{
    __shared__ __align__(16) unsigned char sm[2 * 10240 + 2 * 5120];
    unsigned char* sAhi = sm;
    unsigned char* sAlo = sm + 10240;
    unsigned char* sBhi = sm + 20480;
    unsigned char* sBlo = sm + 25600;

    const int tid = threadIdx.x;
    const int wid = tid >> 5;
    const int lane = tid & 31;
    const int wm = wid & 3;
    const int wn = wid >> 2;
    const int grp = lane >> 2;
    const int tig = lane & 3;
    const int bm = blockIdx.y * 128;
    const int bn = blockIdx.x * 64;

    float acc[2][4][4];
#pragma unroll
    for (int mt = 0; mt < 2; mt++)
#pragma unroll
        for (int nt = 0; nt < 4; nt++)
#pragma unroll
            for (int j = 0; j < 4; j++) acc[mt][nt][j] = 0.f;

    const int lsel = lane >> 3, lrow = lane & 7;
    const uint32_t a_frag_off =
        (uint32_t)((wm * 32 + lrow + (lsel & 1) * 8) * 80 + (lsel >> 1) * 16);
    const uint32_t b_frag_off =
        (uint32_t)((wn * 32 + (lsel >> 1) * 8 + lrow) * 80 + (lsel & 1) * 16);

    const uint32_t sAhi_u = smem_u32(sAhi), sAlo_u = smem_u32(sAlo);
    const uint32_t sBhi_u = smem_u32(sBhi), sBlo_u = smem_u32(sBlo);

    const int nch = K / 32;
    uint4 pah[2], pal[2], pbh, pbl;

    {
#pragma unroll
        for (int it = 0; it < 2; it++) {
            int id = tid + it * 256;
            int row = id >> 2, kq = id & 3;
            int rg = bm + row; if (rg > M - 1) rg = M - 1;
            pah[it] = *(const uint4*)(Ahi + (size_t)rg * K + kq * 8);
            pal[it] = *(const uint4*)(Alo + (size_t)rg * K + kq * 8);
        }
        {
            int row = tid >> 2, kq = tid & 3;
            pbh = *(const uint4*)(BThi + (size_t)(bn + row) * K + kq * 8);
            pbl = *(const uint4*)(BTlo + (size_t)(bn + row) * K + kq * 8);
        }
#pragma unroll
        for (int it = 0; it < 2; it++) {
            int id = tid + it * 256;
            int row = id >> 2, kq = id & 3;
            *(uint4*)(sAhi + row * 80 + kq * 16) = pah[it];
            *(uint4*)(sAlo + row * 80 + kq * 16) = pal[it];
        }
        {
            int row = tid >> 2, kq = tid & 3;
            *(uint4*)(sBhi + row * 80 + kq * 16) = pbh;
            *(uint4*)(sBlo + row * 80 + kq * 16) = pbl;
        }
    }
    __syncthreads();

    for (int ch = 0; ch < nch; ch++) {
        const bool has_next = (ch + 1 < nch);
        if (has_next) {
            const int k0 = (ch + 1) * 32;
#pragma unroll
            for (int it = 0; it < 2; it++) {
                int id = tid + it * 256;
                int row = id >> 2, kq = id & 3;
                int rg = bm + row; if (rg > M - 1) rg = M - 1;
                pah[it] = *(const uint4*)(Ahi + (size_t)rg * K + k0 + kq * 8);
                pal[it] = *(const uint4*)(Alo + (size_t)rg * K + k0 + kq * 8);
            }
            {
                int row = tid >> 2, kq = tid & 3;
                pbh = *(const uint4*)(BThi + (size_t)(bn + row) * K + k0 + kq * 8);
                pbl = *(const uint4*)(BTlo + (size_t)(bn + row) * K + k0 + kq * 8);
            }
        }

#pragma unroll
        for (int kk = 0; kk < 2; kk++) {
            const uint32_t kadd = kk * 32;
            uint32_t ahf[2][4], alf[2][4];
#pragma unroll
            for (int mt = 0; mt < 2; mt++) {
                LDMX4(ahf[mt], sAhi_u + a_frag_off + mt * (16 * 80) + kadd);
                LDMX4(alf[mt], sAlo_u + a_frag_off + mt * (16 * 80) + kadd);
            }
            uint32_t bhf[4][2], blf[4][2];
#pragma unroll
            for (int p = 0; p < 2; p++) {
                uint32_t tmp[4];
                LDMX4(tmp, sBhi_u + b_frag_off + p * (16 * 80) + kadd);
                bhf[2 * p][0] = tmp[0]; bhf[2 * p][1] = tmp[1];
                bhf[2 * p + 1][0] = tmp[2]; bhf[2 * p + 1][1] = tmp[3];
                LDMX4(tmp, sBlo_u + b_frag_off + p * (16 * 80) + kadd);
                blf[2 * p][0] = tmp[0]; blf[2 * p][1] = tmp[1];
                blf[2 * p + 1][0] = tmp[2]; blf[2 * p + 1][1] = tmp[3];
            }
#pragma unroll
            for (int mt = 0; mt < 2; mt++)
#pragma unroll
                for (int nt = 0; nt < 4; nt++) {
                    MMA16816(acc[mt][nt], ahf[mt], bhf[nt]);
                    MMA16816(acc[mt][nt], ahf[mt], blf[nt]);
                    MMA16816(acc[mt][nt], alf[mt], bhf[nt]);
                }
        }

        if (has_next) {
            __syncthreads();
#pragma unroll
            for (int it = 0; it < 2; it++) {
                int id = tid + it * 256;
                int row = id >> 2, kq = id & 3;
                *(uint4*)(sAhi + row * 80 + kq * 16) = pah[it];
                *(uint4*)(sAlo + row * 80 + kq * 16) = pal[it];
            }
            {
                int row = tid >> 2, kq = tid & 3;
                *(uint4*)(sBhi + row * 80 + kq * 16) = pbh;
                *(uint4*)(sBlo + row * 80 + kq * 16) = pbl;
            }
            __syncthreads();
        }
    }

#pragma unroll
    for (int mt = 0; mt < 2; mt++) {
#pragma unroll
        for (int nt = 0; nt < 4; nt++) {
            int row0 = bm + wm * 32 + mt * 16 + grp;
            int col  = bn + wn * 32 + nt * 8 + tig * 2;
            float b0 = bias[col], b1 = bias[col + 1];
            if (row0 < M) {
                float2 o;
                o.x = fmaxf(acc[mt][nt][0] + b0, 0.f);
                o.y = fmaxf(acc[mt][nt][1] + b1, 0.f);
                *(float2*)(C + (size_t)row0 * 512 + col) = o;
            }
            if (row0 + 8 < M) {
                float2 o;
                o.x = fmaxf(acc[mt][nt][2] + b0, 0.f);
                o.y = fmaxf(acc[mt][nt][3] + b1, 0.f);
                *(float2*)(C + (size_t)(row0 + 8) * 512 + col) = o;
            }
        }
    }
}

// ============================================================================
// Kernel 3: fused atom-LN + residue max -> bf16 hi/lo residue features.
// ============================================================================
__global__ __launch_bounds__(256) void ln_resmax_kernel(
    const float* __restrict__ g, const float* __restrict__ be)
{
    const int res = blockIdx.x;
    const int tid = threadIdx.x;
    const int w = tid >> 5, lane = tid & 31;

    __shared__ float buf[8][512];

    const float* hp = g_H + ((size_t)res * 8 + w) * 512;
    float v[16];
    float s = 0.f, s2 = 0.f;
#pragma unroll
    for (int i = 0; i < 16; i++) {
        v[i] = hp[lane + i * 32];
        s += v[i];
        s2 = fmaf(v[i], v[i], s2);
    }
#pragma unroll
    for (int off = 16; off; off >>= 1) {
        s  += __shfl_xor_sync(0xffffffffu, s, off);
        s2 += __shfl_xor_sync(0xffffffffu, s2, off);
    }
    float mu  = s * (1.f / 512.f);
    float var = fmaxf(s2 * (1.f / 512.f) - mu * mu, 0.f);
    float rs  = rsqrtf(var + LN_EPS);
#pragma unroll
    for (int i = 0; i < 16; i++) {
        int c = lane + i * 32;
        buf[w][c] = fmaf(g[c] * (v[i] - mu), rs, be[c]);
    }
    __syncthreads();

#pragma unroll
    for (int rep = 0; rep < 2; rep++) {
        int c = tid + rep * 256;
        float m = buf[0][c];
#pragma unroll
        for (int j = 1; j < 8; j++) m = fmaxf(m, buf[j][c]);
        size_t idx = (size_t)res * 512 + c;
        __nv_bfloat16 hi = __float2bfloat16(m);
        g_REShi[idx] = hi;
        g_RESlo[idx] = __float2bfloat16(m - __bfloat162float(hi));
    }
}

// ============================================================================
// Kernel 4: fused res-LN + lin1 dot
// ============================================================================
__global__ __launch_bounds__(256) void ln_dot_kernel(
    const float* __restrict__ g, const float* __restrict__ be,
    const float* __restrict__ w1)
{
    const int row = blockIdx.x * 8 + (threadIdx.x >> 5);
    const int lane = threadIdx.x & 31;
    if (row >= MR) return;
    const float* hp = g_HR + (size_t)row * 512;

    float v[16];
    float s = 0.f, s2 = 0.f;
#pragma unroll
    for (int i = 0; i < 16; i++) {
        v[i] = hp[lane + i * 32];
        s += v[i];
        s2 = fmaf(v[i], v[i], s2);
    }
#pragma unroll
    for (int off = 16; off; off >>= 1) {
        s  += __shfl_xor_sync(0xffffffffu, s, off);
        s2 += __shfl_xor_sync(0xffffffffu, s2, off);
    }
    float mu  = s * (1.f / 512.f);
    float var = fmaxf(s2 * (1.f / 512.f) - mu * mu, 0.f);
    float rs  = rsqrtf(var + LN_EPS);

    float acc = 0.f;
#pragma unroll
    for (int i = 0; i < 16; i++) {
        int c = lane + i * 32;
        float x = fmaf(g[c] * (v[i] - mu), rs, be[c]);
        acc = fmaf(x, w1[c], acc);
    }
#pragma unroll
    for (int off = 16; off; off >>= 1)
        acc += __shfl_xor_sync(0xffffffffu, acc, off);
    if (lane == 0) g_Y[row] = acc;
}

// ============================================================================
// Kernel 5: pair head
// ============================================================================
__global__ __launch_bounds__(256) void pair_kernel(
    const int* __restrict__ srcI, const int* __restrict__ tgtI,
    const float* __restrict__ b1, float* __restrict__ out)
{
    const int p = blockIdx.x * 256 + threadIdx.x;
    if (p >= PP) return;
    float x = g_Y[srcI[p]] - g_Y[RR + tgtI[p]] + b1[0];
    out[p] = 1.f / (1.f + expf(-x));
}

// ============================================================================
extern "C" void kernel_launch(void* const* d_in, const int* in_sizes, int n_in,
                              void* d_out, int out_size)
{
    const float* posA = (const float*)d_in[0];
    const float* nrmA = (const float*)d_in[1];
    const float* posB = (const float*)d_in[2];
    const float* nrmB = (const float*)d_in[3];
    const int*   edgA = (const int*)d_in[4];
    const int*   edgB = (const int*)d_in[5];
    const int*   srcI = (const int*)d_in[8];
    const int*   tgtI = (const int*)d_in[9];

    int w = (in_sizes[10] == 48) ? 10 : 11;
    const float* cw1   = (const float*)d_in[w++];
    const float* cb1   = (const float*)d_in[w++];
    const float* cg1   = (const float*)d_in[w++];
    const float* cbe1  = (const float*)d_in[w++];
    const float* cw2   = (const float*)d_in[w++];
    const float* cb2   = (const float*)d_in[w++];
    const float* cg2   = (const float*)d_in[w++];
    const float* cbe2  = (const float*)d_in[w++];
    const float* atomW = (const float*)d_in[w++];
    const float* atomB = (const float*)d_in[w++];
    const float* atomG = (const float*)d_in[w++];
    const float* atomBe= (const float*)d_in[w++];
    const float* resW  = (const float*)d_in[w++];
    const float* resB  = (const float*)d_in[w++];
    const float* resG  = (const float*)d_in[w++];
    const float* resBe = (const float*)d_in[w++];
    const float* lin1W = (const float*)d_in[w++];
    const float* lin1B = (const float*)d_in[w++];

    float* out = (float*)d_out;

    __nv_bfloat16 *wthi, *wtlo, *w2hi, *w2lo, *ahi, *alo, *rhi, *rlo;
    cudaGetSymbolAddress((void**)&wthi, g_WThi);
    cudaGetSymbolAddress((void**)&wtlo, g_WTlo);
    cudaGetSymbolAddress((void**)&w2hi, g_W2hi);
    cudaGetSymbolAddress((void**)&w2lo, g_W2lo);
    cudaGetSymbolAddress((void**)&ahi,  g_Ahi);
    cudaGetSymbolAddress((void**)&alo,  g_Alo);
    cudaGetSymbolAddress((void**)&rhi,  g_REShi);
    cudaGetSymbolAddress((void**)&rlo,  g_RESlo);
    float *gH, *gHR;
    cudaGetSymbolAddress((void**)&gH,  g_H);
    cudaGetSymbolAddress((void**)&gHR, g_HR);

    // 1. edge convs -> g_Ahi/g_Alo [24000,384] bf16 split
    edgeconv_kernel<<<dim3(NA / NPB, 3, 2), 128>>>(
        posA, nrmA, edgA, posB, nrmB, edgB,
        cw1, cb1, cg1, cbe1, cw2, cb2, cg2, cbe2);
    // 1b. weight transposes + splits
    convert_wT_kernel<<<(512 * 384 + 255) / 256, 256>>>(atomW, wthi, wtlo, 384);
    convert_wT_kernel<<<(512 * 512 + 255) / 256, 256>>>(resW,  w2hi, w2lo, 512);
    // 2. atom MLP (HMMA + ldmatrix) -> g_H
    gemm_mma_kernel<<<dim3(8, (MA + 127) / 128), 256>>>(
        ahi, alo, wthi, wtlo, atomB, gH, MA, 384);
    // 3. fused atom-LN + residue max -> g_REShi/lo
    ln_resmax_kernel<<<MR, 256>>>(atomG, atomBe);
    // 4. res MLP (HMMA + ldmatrix) -> g_HR
    gemm_mma_kernel<<<dim3(8, (MR + 127) / 128), 256>>>(
        rhi, rlo, w2hi, w2lo, resB, gHR, MR, 512);
    // 5. fused res-LN + lin1 dot -> g_Y
    ln_dot_kernel<<<(MR + 7) / 8, 256>>>(resG, resBe, lin1W);
    // 6. pair head
    pair_kernel<<<(PP + 255) / 256, 256>>>(srcI, tgtI, lin1B, out);
}

// round 17
// speedup vs baseline: 2.4900x; 1.3204x over previous
#include <cuda_runtime.h>
#include <cuda_bf16.h>
#include <math.h>
#include <float.h>
#include <stdint.h>

#define NA 12000
#define KNB 32
#define EE (NA*KNB)
#define RR 1500
#define PP 4096
#define MA (2*NA)      /* 24000 atom rows (A then B) */
#define MR (2*RR)      /* 3000 residue rows */
#define LN_EPS 1e-5f
#define NPB 8          /* nodes per edgeconv block */

// ---- scratch (static device globals; no allocation) ----
__device__ __nv_bfloat16 g_Ahi[MA * 384];    // edgeconv out hi [24000,384]
__device__ __nv_bfloat16 g_Alo[MA * 384];
__device__ __nv_bfloat16 g_WThi[512 * 384];  // atom_w^T [512,384]
__device__ __nv_bfloat16 g_WTlo[512 * 384];
__device__ __nv_bfloat16 g_W2hi[512 * 512];  // res_w^T  [512,512]
__device__ __nv_bfloat16 g_W2lo[512 * 512];
__device__ __nv_bfloat16 g_REShi[MR * 512];  // residue max [3000,512]
__device__ __nv_bfloat16 g_RESlo[MR * 512];
__device__ float g_H[MA * 512];       // atom MLP relu output (pre-LN)
__device__ float g_HR[MR * 512];      // res MLP relu output (pre-LN)
__device__ float g_Y[MR];             // per-residue scalar: LN(row) . lin1_w

__device__ __forceinline__ float angle3(float ax, float ay, float az,
                                        float bx, float by, float bz) {
    float cx = ay * bz - az * by;
    float cy = az * bx - ax * bz;
    float cz = ax * by - ay * bx;
    float cn = sqrtf(cx * cx + cy * cy + cz * cz);
    float d  = ax * bx + ay * by + az * bz;
    return atan2f(cn, d);
}

#define MMA16816(c, a, b) \
  asm volatile("mma.sync.aligned.m16n8k16.row.col.f32.bf16.bf16.f32 " \
    "{%0,%1,%2,%3}, {%4,%5,%6,%7}, {%8,%9}, {%0,%1,%2,%3};" \
    : "+f"((c)[0]), "+f"((c)[1]), "+f"((c)[2]), "+f"((c)[3]) \
    : "r"((a)[0]), "r"((a)[1]), "r"((a)[2]), "r"((a)[3]), \
      "r"((b)[0]), "r"((b)[1]))

#define LDMX4(r, addr) \
  asm volatile("ldmatrix.sync.aligned.m8n8.x4.shared.b16 {%0,%1,%2,%3}, [%4];" \
    : "=r"((r)[0]), "=r"((r)[1]), "=r"((r)[2]), "=r"((r)[3]) : "r"(addr))

__device__ __forceinline__ uint32_t smem_u32(const void* p) {
    uint32_t a;
    asm("{ .reg .u64 t; cvta.to.shared.u64 t, %1; cvt.u32.u64 %0, t; }"
        : "=r"(a) : "l"(p));
    return a;
}

// ============================================================================
// Kernel 1: fused PPF + MLP(4->4,LN) + MLP(4->128,LN) + max over 32 edges.
// Channel-per-thread layer 2 (weights in registers), batched PPF phase,
// z kept in registers through the LN-max pass.
// ============================================================================
__global__ __launch_bounds__(128) void edgeconv_kernel(
    const float* __restrict__ posA, const float* __restrict__ nrmA, const int* __restrict__ edgA,
    const float* __restrict__ posB, const float* __restrict__ nrmB, const int* __restrict__ edgB,
    const float* __restrict__ cw1, const float* __restrict__ cb1,
    const float* __restrict__ cg1, const float* __restrict__ cbe1,
    const float* __restrict__ cw2, const float* __restrict__ cb2,
    const float* __restrict__ cg2, const float* __restrict__ cbe2)
{
    const int r    = blockIdx.y;
    const int side = blockIdx.z;
    const float* pos = side ? posB : posA;
    const float* nrm = side ? nrmB : nrmA;
    const int*   edg = side ? edgB : edgA;
    const int tid = threadIdx.x;      // == channel c in phases A/C

    __shared__ float4 hnbuf[NPB * 32];          // layer-1 outputs, all nodes
    __shared__ float w1s[16], b1s[4], g1s[4], be1s[4];
    __shared__ float zbuf[32 * 132];            // per-node z, padded stride
    __shared__ float mus[32], rss[32];

    // layer-2 params for this thread's channel -> registers (once per block)
    const float wc0 = cw2[r * 512 + 0 * 128 + tid];
    const float wc1 = cw2[r * 512 + 1 * 128 + tid];
    const float wc2v = cw2[r * 512 + 2 * 128 + tid];
    const float wc3 = cw2[r * 512 + 3 * 128 + tid];
    const float bc  = cb2[r * 128 + tid];
    const float gac = cg2[r * 128 + tid];
    const float bec = cbe2[r * 128 + tid];

    if (tid < 16) w1s[tid] = cw1[r * 16 + tid];
    if (tid < 4) {
        b1s[tid]  = cb1[r * 4 + tid];
        g1s[tid]  = cg1[r * 4 + tid];
        be1s[tid] = cbe1[r * 4 + tid];
    }
    __syncthreads();

    // ---- Phase 0: PPF + layer1 for all NPB*32 (node,edge) tasks ----
#pragma unroll
    for (int t = tid; t < NPB * 32; t += 128) {
        const int nn = t >> 5, e = t & 31;
        const int node = blockIdx.x * NPB + nn;
        const int src = __ldg(&edg[r * 2 * EE + node * KNB + e]);
        const float dx = pos[src * 3 + 0] - pos[node * 3 + 0];
        const float dy = pos[src * 3 + 1] - pos[node * 3 + 1];
        const float dz = pos[src * 3 + 2] - pos[node * 3 + 2];
        const float nix = nrm[node * 3 + 0], niy = nrm[node * 3 + 1], niz = nrm[node * 3 + 2];
        const float njx = nrm[src * 3 + 0], njy = nrm[src * 3 + 1], njz = nrm[src * 3 + 2];
        const float f0 = sqrtf(dx * dx + dy * dy + dz * dz);
        const float f1 = angle3(nix, niy, niz, dx, dy, dz);
        const float f2 = angle3(njx, njy, njz, dx, dy, dz);
        const float f3 = angle3(nix, niy, niz, njx, njy, njz);

        float h[4];
#pragma unroll
        for (int k = 0; k < 4; k++) {
            float v = fmaf(f0, w1s[k],
                      fmaf(f1, w1s[4 + k],
                      fmaf(f2, w1s[8 + k],
                      fmaf(f3, w1s[12 + k], b1s[k]))));
            h[k] = fmaxf(v, 0.f);
        }
        float mu1 = 0.25f * (h[0] + h[1] + h[2] + h[3]);
        float var1 = 0.25f * ((h[0]-mu1)*(h[0]-mu1) + (h[1]-mu1)*(h[1]-mu1)
                            + (h[2]-mu1)*(h[2]-mu1) + (h[3]-mu1)*(h[3]-mu1));
        float rs1 = rsqrtf(var1 + LN_EPS);
        float4 hn;
        hn.x = fmaf(g1s[0] * (h[0] - mu1), rs1, be1s[0]);
        hn.y = fmaf(g1s[1] * (h[1] - mu1), rs1, be1s[1]);
        hn.z = fmaf(g1s[2] * (h[2] - mu1), rs1, be1s[2]);
        hn.w = fmaf(g1s[3] * (h[3] - mu1), rs1, be1s[3]);
        hnbuf[t] = hn;
    }
    __syncthreads();

    const int e2 = tid >> 2;      // stats mapping
    const int q  = tid & 3;

    for (int nn = 0; nn < NPB; nn++) {
        // ---- Phase A: layer 2, channel-per-thread; z stays in registers ----
        float z[32];
#pragma unroll
        for (int e = 0; e < 32; e++) {
            float4 h = hnbuf[nn * 32 + e];           // warp-uniform broadcast
            float v = fmaf(h.x, wc0,
                      fmaf(h.y, wc1,
                      fmaf(h.z, wc2v,
                      fmaf(h.w, wc3, bc))));
            v = fmaxf(v, 0.f);
            z[e] = v;
            zbuf[e * 132 + tid] = v;
        }
        __syncthreads();

        // ---- Phase B: per-edge LN stats (4 threads per edge) ----
        {
            float s = 0.f, s2 = 0.f;
#pragma unroll
            for (int i = q; i < 128; i += 4) {
                float zz = zbuf[e2 * 132 + i];
                s += zz;
                s2 = fmaf(zz, zz, s2);
            }
            s  += __shfl_xor_sync(0xffffffffu, s, 1);
            s  += __shfl_xor_sync(0xffffffffu, s, 2);
            s2 += __shfl_xor_sync(0xffffffffu, s2, 1);
            s2 += __shfl_xor_sync(0xffffffffu, s2, 2);
            if (q == 0) {
                float mu  = s * (1.f / 128.f);
                float var = fmaxf(s2 * (1.f / 128.f) - mu * mu, 0.f);
                mus[e2] = mu;
                rss[e2] = rsqrtf(var + LN_EPS);
            }
        }
        __syncthreads();

        // ---- Phase C: LN + max over edges (z already in registers) ----
        float m = -FLT_MAX;
#pragma unroll
        for (int e = 0; e < 32; e++) {
            float t = (z[e] - mus[e]) * rss[e];
            m = fmaxf(m, fmaf(gac, t, bec));
        }
        const int node = blockIdx.x * NPB + nn;
        size_t idx = (size_t)(side * NA + node) * 384 + r * 128 + tid;
        __nv_bfloat16 hi = __float2bfloat16(m);
        g_Ahi[idx] = hi;
        g_Alo[idx] = __float2bfloat16(m - __bfloat162float(hi));
        // no sync needed here: next Phase A writes zbuf (Phase B done reading
        // before sync above); next Phase B (which overwrites mus/rss) is
        // separated from this Phase C by the sync after next Phase A.
    }
}

// ============================================================================
// Kernel 1b: transpose + bf16-split  src[K,512] -> dst hi/lo [512,K]
// ============================================================================
__global__ __launch_bounds__(256) void convert_wT_kernel(
    const float* __restrict__ src, __nv_bfloat16* __restrict__ dhi,
    __nv_bfloat16* __restrict__ dlo, int K)
{
    int i = blockIdx.x * 256 + threadIdx.x;
    if (i >= 512 * K) return;
    int n = i / K, k = i % K;
    float v = src[k * 512 + n];
    __nv_bfloat16 hi = __float2bfloat16(v);
    dhi[i] = hi;
    dlo[i] = __float2bfloat16(v - __bfloat162float(hi));
}

// ============================================================================
// Kernel 2: HMMA bf16-split GEMM with ldmatrix fragment loads.
// C[M,512] = relu(A @ BT^T + bias); 3 mma terms -> fp32 accum.
// Block tile 128x64, 8 warps (4m x 2n), warp tile 32x32, BK=32.
// ============================================================================
__global__ __launch_bounds__(256, 2) void gemm_mma_kernel(
    const __nv_bfloat16* __restrict__ Ahi, const __nv_bfloat16* __restrict__ Alo,
    const __nv_bfloat16* __restrict__ BThi, const __nv_bfloat16* __restrict__ BTlo,
    const float* __restrict__ bias, float* __restrict__ C, int M, int K)
{
    __shared__ __align__(16) unsigned char sm[2 * 10240 + 2 * 5120];
    unsigned char* sAhi = sm;
    unsigned char* sAlo = sm + 10240;
    unsigned char* sBhi = sm + 20480;
    unsigned char* sBlo = sm + 25600;

    const int tid = threadIdx.x;
    const int wid = tid >> 5;
    const int lane = tid & 31;
    const int wm = wid & 3;
    const int wn = wid >> 2;
    const int grp = lane >> 2;
    const int tig = lane & 3;
    const int bm = blockIdx.y * 128;
    const int bn = blockIdx.x * 64;

    float acc[2][4][4];
#pragma unroll
    for (int mt = 0; mt < 2; mt++)
#pragma unroll
        for (int nt = 0; nt < 4; nt++)
#pragma unroll
            for (int j = 0; j < 4; j++) acc[mt][nt][j] = 0.f;

    const int lsel = lane >> 3, lrow = lane & 7;
    const uint32_t a_frag_off =
        (uint32_t)((wm * 32 + lrow + (lsel & 1) * 8) * 80 + (lsel >> 1) * 16);
    const uint32_t b_frag_off =
        (uint32_t)((wn * 32 + (lsel >> 1) * 8 + lrow) * 80 + (lsel & 1) * 16);

    const uint32_t sAhi_u = smem_u32(sAhi), sAlo_u = smem_u32(sAlo);
    const uint32_t sBhi_u = smem_u32(sBhi), sBlo_u = smem_u32(sBlo);

    const int nch = K / 32;
    uint4 pah[2], pal[2], pbh, pbl;

    {
#pragma unroll
        for (int it = 0; it < 2; it++) {
            int id = tid + it * 256;
            int row = id >> 2, kq = id & 3;
            int rg = bm + row; if (rg > M - 1) rg = M - 1;
            pah[it] = *(const uint4*)(Ahi + (size_t)rg * K + kq * 8);
            pal[it] = *(const uint4*)(Alo + (size_t)rg * K + kq * 8);
        }
        {
            int row = tid >> 2, kq = tid & 3;
            pbh = *(const uint4*)(BThi + (size_t)(bn + row) * K + kq * 8);
            pbl = *(const uint4*)(BTlo + (size_t)(bn + row) * K + kq * 8);
        }
#pragma unroll
        for (int it = 0; it < 2; it++) {
            int id = tid + it * 256;
            int row = id >> 2, kq = id & 3;
            *(uint4*)(sAhi + row * 80 + kq * 16) = pah[it];
            *(uint4*)(sAlo + row * 80 + kq * 16) = pal[it];
        }
        {
            int row = tid >> 2, kq = tid & 3;
            *(uint4*)(sBhi + row * 80 + kq * 16) = pbh;
            *(uint4*)(sBlo + row * 80 + kq * 16) = pbl;
        }
    }
    __syncthreads();

    for (int ch = 0; ch < nch; ch++) {
        const bool has_next = (ch + 1 < nch);
        if (has_next) {
            const int k0 = (ch + 1) * 32;
#pragma unroll
            for (int it = 0; it < 2; it++) {
                int id = tid + it * 256;
                int row = id >> 2, kq = id & 3;
                int rg = bm + row; if (rg > M - 1) rg = M - 1;
                pah[it] = *(const uint4*)(Ahi + (size_t)rg * K + k0 + kq * 8);
                pal[it] = *(const uint4*)(Alo + (size_t)rg * K + k0 + kq * 8);
            }
            {
                int row = tid >> 2, kq = tid & 3;
                pbh = *(const uint4*)(BThi + (size_t)(bn + row) * K + k0 + kq * 8);
                pbl = *(const uint4*)(BTlo + (size_t)(bn + row) * K + k0 + kq * 8);
            }
        }

#pragma unroll
        for (int kk = 0; kk < 2; kk++) {
            const uint32_t kadd = kk * 32;
            uint32_t ahf[2][4], alf[2][4];
#pragma unroll
            for (int mt = 0; mt < 2; mt++) {
                LDMX4(ahf[mt], sAhi_u + a_frag_off + mt * (16 * 80) + kadd);
                LDMX4(alf[mt], sAlo_u + a_frag_off + mt * (16 * 80) + kadd);
            }
            uint32_t bhf[4][2], blf[4][2];
#pragma unroll
            for (int p = 0; p < 2; p++) {
                uint32_t tmp[4];
                LDMX4(tmp, sBhi_u + b_frag_off + p * (16 * 80) + kadd);
                bhf[2 * p][0] = tmp[0]; bhf[2 * p][1] = tmp[1];
                bhf[2 * p + 1][0] = tmp[2]; bhf[2 * p + 1][1] = tmp[3];
                LDMX4(tmp, sBlo_u + b_frag_off + p * (16 * 80) + kadd);
                blf[2 * p][0] = tmp[0]; blf[2 * p][1] = tmp[1];
                blf[2 * p + 1][0] = tmp[2]; blf[2 * p + 1][1] = tmp[3];
            }
#pragma unroll
            for (int mt = 0; mt < 2; mt++)
#pragma unroll
                for (int nt = 0; nt < 4; nt++) {
                    MMA16816(acc[mt][nt], ahf[mt], bhf[nt]);
                    MMA16816(acc[mt][nt], ahf[mt], blf[nt]);
                    MMA16816(acc[mt][nt], alf[mt], bhf[nt]);
                }
        }

        if (has_next) {
            __syncthreads();
#pragma unroll
            for (int it = 0; it < 2; it++) {
                int id = tid + it * 256;
                int row = id >> 2, kq = id & 3;
                *(uint4*)(sAhi + row * 80 + kq * 16) = pah[it];
                *(uint4*)(sAlo + row * 80 + kq * 16) = pal[it];
            }
            {
                int row = tid >> 2, kq = tid & 3;
                *(uint4*)(sBhi + row * 80 + kq * 16) = pbh;
                *(uint4*)(sBlo + row * 80 + kq * 16) = pbl;
            }
            __syncthreads();
        }
    }

#pragma unroll
    for (int mt = 0; mt < 2; mt++) {
#pragma unroll
        for (int nt = 0; nt < 4; nt++) {
            int row0 = bm + wm * 32 + mt * 16 + grp;
            int col  = bn + wn * 32 + nt * 8 + tig * 2;
            float b0 = bias[col], b1 = bias[col + 1];
            if (row0 < M) {
                float2 o;
                o.x = fmaxf(acc[mt][nt][0] + b0, 0.f);
                o.y = fmaxf(acc[mt][nt][1] + b1, 0.f);
                *(float2*)(C + (size_t)row0 * 512 + col) = o;
            }
            if (row0 + 8 < M) {
                float2 o;
                o.x = fmaxf(acc[mt][nt][2] + b0, 0.f);
                o.y = fmaxf(acc[mt][nt][3] + b1, 0.f);
                *(float2*)(C + (size_t)(row0 + 8) * 512 + col) = o;
            }
        }
    }
}

// ============================================================================
// Kernel 3: fused atom-LN + residue max -> bf16 hi/lo residue features.
// ============================================================================
__global__ __launch_bounds__(256) void ln_resmax_kernel(
    const float* __restrict__ g, const float* __restrict__ be)
{
    const int res = blockIdx.x;
    const int tid = threadIdx.x;
    const int w = tid >> 5, lane = tid & 31;

    __shared__ float buf[8][512];

    const float* hp = g_H + ((size_t)res * 8 + w) * 512;
    float v[16];
    float s = 0.f, s2 = 0.f;
#pragma unroll
    for (int i = 0; i < 16; i++) {
        v[i] = hp[lane + i * 32];
        s += v[i];
        s2 = fmaf(v[i], v[i], s2);
    }
#pragma unroll
    for (int off = 16; off; off >>= 1) {
        s  += __shfl_xor_sync(0xffffffffu, s, off);
        s2 += __shfl_xor_sync(0xffffffffu, s2, off);
    }
    float mu  = s * (1.f / 512.f);
    float var = fmaxf(s2 * (1.f / 512.f) - mu * mu, 0.f);
    float rs  = rsqrtf(var + LN_EPS);
#pragma unroll
    for (int i = 0; i < 16; i++) {
        int c = lane + i * 32;
        buf[w][c] = fmaf(g[c] * (v[i] - mu), rs, be[c]);
    }
    __syncthreads();

#pragma unroll
    for (int rep = 0; rep < 2; rep++) {
        int c = tid + rep * 256;
        float m = buf[0][c];
#pragma unroll
        for (int j = 1; j < 8; j++) m = fmaxf(m, buf[j][c]);
        size_t idx = (size_t)res * 512 + c;
        __nv_bfloat16 hi = __float2bfloat16(m);
        g_REShi[idx] = hi;
        g_RESlo[idx] = __float2bfloat16(m - __bfloat162float(hi));
    }
}

// ============================================================================
// Kernel 4: fused res-LN + lin1 dot
// ============================================================================
__global__ __launch_bounds__(256) void ln_dot_kernel(
    const float* __restrict__ g, const float* __restrict__ be,
    const float* __restrict__ w1)
{
    const int row = blockIdx.x * 8 + (threadIdx.x >> 5);
    const int lane = threadIdx.x & 31;
    if (row >= MR) return;
    const float* hp = g_HR + (size_t)row * 512;

    float v[16];
    float s = 0.f, s2 = 0.f;
#pragma unroll
    for (int i = 0; i < 16; i++) {
        v[i] = hp[lane + i * 32];
        s += v[i];
        s2 = fmaf(v[i], v[i], s2);
    }
#pragma unroll
    for (int off = 16; off; off >>= 1) {
        s  += __shfl_xor_sync(0xffffffffu, s, off);
        s2 += __shfl_xor_sync(0xffffffffu, s2, off);
    }
    float mu  = s * (1.f / 512.f);
    float var = fmaxf(s2 * (1.f / 512.f) - mu * mu, 0.f);
    float rs  = rsqrtf(var + LN_EPS);

    float acc = 0.f;
#pragma unroll
    for (int i = 0; i < 16; i++) {
        int c = lane + i * 32;
        float x = fmaf(g[c] * (v[i] - mu), rs, be[c]);
        acc = fmaf(x, w1[c], acc);
    }
#pragma unroll
    for (int off = 16; off; off >>= 1)
        acc += __shfl_xor_sync(0xffffffffu, acc, off);
    if (lane == 0) g_Y[row] = acc;
}

// ============================================================================
// Kernel 5: pair head
// ============================================================================
__global__ __launch_bounds__(256) void pair_kernel(
    const int* __restrict__ srcI, const int* __restrict__ tgtI,
    const float* __restrict__ b1, float* __restrict__ out)
{
    const int p = blockIdx.x * 256 + threadIdx.x;
    if (p >= PP) return;
    float x = g_Y[srcI[p]] - g_Y[RR + tgtI[p]] + b1[0];
    out[p] = 1.f / (1.f + expf(-x));
}

// ============================================================================
extern "C" void kernel_launch(void* const* d_in, const int* in_sizes, int n_in,
                              void* d_out, int out_size)
{
    const float* posA = (const float*)d_in[0];
    const float* nrmA = (const float*)d_in[1];
    const float* posB = (const float*)d_in[2];
    const float* nrmB = (const float*)d_in[3];
    const int*   edgA = (const int*)d_in[4];
    const int*   edgB = (const int*)d_in[5];
    const int*   srcI = (const int*)d_in[8];
    const int*   tgtI = (const int*)d_in[9];

    int w = (in_sizes[10] == 48) ? 10 : 11;
    const float* cw1   = (const float*)d_in[w++];
    const float* cb1   = (const float*)d_in[w++];
    const float* cg1   = (const float*)d_in[w++];
    const float* cbe1  = (const float*)d_in[w++];
    const float* cw2   = (const float*)d_in[w++];
    const float* cb2   = (const float*)d_in[w++];
    const float* cg2   = (const float*)d_in[w++];
    const float* cbe2  = (const float*)d_in[w++];
    const float* atomW = (const float*)d_in[w++];
    const float* atomB = (const float*)d_in[w++];
    const float* atomG = (const float*)d_in[w++];
    const float* atomBe= (const float*)d_in[w++];
    const float* resW  = (const float*)d_in[w++];
    const float* resB  = (const float*)d_in[w++];
    const float* resG  = (const float*)d_in[w++];
    const float* resBe = (const float*)d_in[w++];
    const float* lin1W = (const float*)d_in[w++];
    const float* lin1B = (const float*)d_in[w++];

    float* out = (float*)d_out;

    __nv_bfloat16 *wthi, *wtlo, *w2hi, *w2lo, *ahi, *alo, *rhi, *rlo;
    cudaGetSymbolAddress((void**)&wthi, g_WThi);
    cudaGetSymbolAddress((void**)&wtlo, g_WTlo);
    cudaGetSymbolAddress((void**)&w2hi, g_W2hi);
    cudaGetSymbolAddress((void**)&w2lo, g_W2lo);
    cudaGetSymbolAddress((void**)&ahi,  g_Ahi);
    cudaGetSymbolAddress((void**)&alo,  g_Alo);
    cudaGetSymbolAddress((void**)&rhi,  g_REShi);
    cudaGetSymbolAddress((void**)&rlo,  g_RESlo);
    float *gH, *gHR;
    cudaGetSymbolAddress((void**)&gH,  g_H);
    cudaGetSymbolAddress((void**)&gHR, g_HR);

    // 1. edge convs -> g_Ahi/g_Alo [24000,384] bf16 split
    edgeconv_kernel<<<dim3(NA / NPB, 3, 2), 128>>>(
        posA, nrmA, edgA, posB, nrmB, edgB,
        cw1, cb1, cg1, cbe1, cw2, cb2, cg2, cbe2);
    // 1b. weight transposes + splits
    convert_wT_kernel<<<(512 * 384 + 255) / 256, 256>>>(atomW, wthi, wtlo, 384);
    convert_wT_kernel<<<(512 * 512 + 255) / 256, 256>>>(resW,  w2hi, w2lo, 512);
    // 2. atom MLP (HMMA + ldmatrix) -> g_H
    gemm_mma_kernel<<<dim3(8, (MA + 127) / 128), 256>>>(
        ahi, alo, wthi, wtlo, atomB, gH, MA, 384);
    // 3. fused atom-LN + residue max -> g_REShi/lo
    ln_resmax_kernel<<<MR, 256>>>(atomG, atomBe);
    // 4. res MLP (HMMA + ldmatrix) -> g_HR
    gemm_mma_kernel<<<dim3(8, (MR + 127) / 128), 256>>>(
        rhi, rlo, w2hi, w2lo, resB, gHR, MR, 512);
    // 5. fused res-LN + lin1 dot -> g_Y
    ln_dot_kernel<<<(MR + 7) / 8, 256>>>(resG, resBe, lin1W);
    // 6. pair head
    pair_kernel<<<(PP + 255) / 256, 256>>>(srcI, tgtI, lin1B, out);
}